// round 2
// baseline (speedup 1.0000x reference)
#include <cuda_runtime.h>
#include <math.h>

#define BB   2
#define NNODE 2048
#define HID  256
#define NH   4
#define DD   64
#define PL   128

// ---------------- scratch (device globals; no allocation allowed) ----------------
__device__ float g_x0[BB*NNODE*HID];     // input-proj output (4 MB)
__device__ float g_h[BB*NNODE*HID];      // per-layer projected features (4 MB)
__device__ float g_srcv[BB*NNODE*NH];
__device__ float g_dstv[BB*NNODE*NH];
__device__ float g_esp[BB*NNODE*NH];     // exp(src)
__device__ float g_esn[BB*NNODE*NH];     // exp(0.2*src)
__device__ float g_edp[BB*NNODE*NH];     // exp(dst)
__device__ float g_edn[BB*NNODE*NH];     // exp(0.2*dst)
__device__ float g_ps[BB*NNODE];         // pool scores
__device__ float g_pe[BB*NNODE];         // pool exp(score - max)
__device__ float g_pz[BB];               // pool partition
__device__ float g_partial[BB*16*HID];   // pool partial weighted sums

// ---------------- packed f32x2 helpers (sm_103a) ----------------
__device__ __forceinline__ unsigned long long pack2(float v) {
    unsigned long long r;
    asm("mov.b64 %0, {%1, %1};" : "=l"(r) : "f"(v));
    return r;
}
__device__ __forceinline__ void unpack2(unsigned long long v, float& lo, float& hi) {
    asm("mov.b64 {%0, %1}, %2;" : "=f"(lo), "=f"(hi) : "l"(v));
}
__device__ __forceinline__ unsigned long long fma2(unsigned long long a,
                                                   unsigned long long b,
                                                   unsigned long long c) {
    unsigned long long d;
    asm("fma.rn.f32x2 %0, %1, %2, %3;" : "=l"(d) : "l"(a), "l"(b), "l"(c));
    return d;
}

// ---------------- input projection: x = relu(ge * w + b) ----------------
__global__ void k_input(const float* __restrict__ ge,
                        const float* __restrict__ w,
                        const float* __restrict__ b) {
    int idx = blockIdx.x * 256 + threadIdx.x;   // over B*N*HID
    int c = idx & (HID - 1);
    float v = fmaf(ge[idx >> 8], w[c], b[c]);
    g_x0[idx] = v > 0.f ? v : 0.f;
}

// ---------------- attn-pool score: s[n] = sum_p tanh(x@w1 + b1)_p * w2_p ----------------
// (bias b2 omitted: scalar shift is softmax-invariant)
__global__ void k_pool_score(const float* __restrict__ x,
                             const float* __restrict__ w1,
                             const float* __restrict__ b1,
                             const float* __restrict__ w2) {
    __shared__ float xs[8][HID];
    __shared__ float red[4][8];
    int row0 = blockIdx.x * 8;
    int tid = threadIdx.x;   // 128 threads
    const float4* s4 = (const float4*)(x + row0 * HID);
    float4* d4 = (float4*)xs;
#pragma unroll
    for (int k = 0; k < 4; k++) d4[tid + k * 128] = s4[tid + k * 128];
    __syncthreads();

    float acc[8];
#pragma unroll
    for (int r = 0; r < 8; r++) acc[r] = 0.f;
    for (int c = 0; c < HID; c++) {
        float wv = w1[c * PL + tid];
#pragma unroll
        for (int r = 0; r < 8; r++) acc[r] = fmaf(xs[r][c], wv, acc[r]);
    }
    float bv = b1[tid], w2v = w2[tid];
    int lane = tid & 31, wp = tid >> 5;
#pragma unroll
    for (int r = 0; r < 8; r++) {
        float v = tanhf(acc[r] + bv) * w2v;
#pragma unroll
        for (int off = 16; off; off >>= 1) v += __shfl_down_sync(0xffffffffu, v, off);
        if (lane == 0) red[wp][r] = v;
    }
    __syncthreads();
    if (tid < 8)
        g_ps[row0 + tid] = red[0][tid] + red[1][tid] + red[2][tid] + red[3][tid];
}

// ---------------- pool softmax stats: max, exp, Z per batch ----------------
__global__ void k_pool_a() {
    int b = blockIdx.x, tid = threadIdx.x;
    __shared__ float red[256];
    float m = -1e30f;
    for (int n = tid; n < NNODE; n += 256) m = fmaxf(m, g_ps[b * NNODE + n]);
    red[tid] = m; __syncthreads();
    for (int s = 128; s > 0; s >>= 1) { if (tid < s) red[tid] = fmaxf(red[tid], red[tid + s]); __syncthreads(); }
    m = red[0]; __syncthreads();
    float z = 0.f;
    for (int n = tid; n < NNODE; n += 256) {
        float e = expf(g_ps[b * NNODE + n] - m);
        g_pe[b * NNODE + n] = e;
        z += e;
    }
    red[tid] = z; __syncthreads();
    for (int s = 128; s > 0; s >>= 1) { if (tid < s) red[tid] += red[tid + s]; __syncthreads(); }
    if (tid == 0) g_pz[b] = red[0];
}

// ---------------- pool weighted partial sums over n segments ----------------
__global__ void k_pool_b(const float* __restrict__ x) {
    int b = blockIdx.x >> 4, seg = blockIdx.x & 15;
    int c = threadIdx.x;
    int n0 = seg * 128;
    float acc = 0.f;
#pragma unroll 4
    for (int n = n0; n < n0 + 128; n++)
        acc = fmaf(g_pe[b * NNODE + n], x[(b * NNODE + n) * HID + c], acc);
    g_partial[blockIdx.x * HID + c] = acc;
}

__global__ void k_pool_c(float* __restrict__ outp) {
    int b = blockIdx.x, c = threadIdx.x;
    float acc = 0.f;
#pragma unroll
    for (int seg = 0; seg < 16; seg++) acc += g_partial[(b * 16 + seg) * HID + c];
    outp[b * HID + c] = acc / g_pz[b];
}

// ---------------- h = cur @ W (4096x256 @ 256x256) ----------------
__global__ void k_gemm(const float* __restrict__ xin, const float* __restrict__ W) {
    __shared__ float xs[16][HID];
    int row0 = blockIdx.x * 16;
    int tid = threadIdx.x;   // 256 = output column
    const float4* s4 = (const float4*)(xin + row0 * HID);
    float4* d4 = (float4*)xs;
#pragma unroll
    for (int k = 0; k < 4; k++) d4[tid + k * 256] = s4[tid + k * 256];
    __syncthreads();

    float acc[16];
#pragma unroll
    for (int r = 0; r < 16; r++) acc[r] = 0.f;
    for (int c = 0; c < HID; c += 4) {
        float w0 = W[(c + 0) * HID + tid];
        float w1 = W[(c + 1) * HID + tid];
        float w2 = W[(c + 2) * HID + tid];
        float w3 = W[(c + 3) * HID + tid];
#pragma unroll
        for (int r = 0; r < 16; r++) {
            float4 xv = *(const float4*)&xs[r][c];
            acc[r] = fmaf(xv.x, w0, acc[r]);
            acc[r] = fmaf(xv.y, w1, acc[r]);
            acc[r] = fmaf(xv.z, w2, acc[r]);
            acc[r] = fmaf(xv.w, w3, acc[r]);
        }
    }
#pragma unroll
    for (int r = 0; r < 16; r++) g_h[(row0 + r) * HID + tid] = acc[r];
}

// ---------------- src/dst projections + exp tables ----------------
__global__ void k_srcdst(const float* __restrict__ asrc, const float* __restrict__ adst) {
    int warp = (blockIdx.x * blockDim.x + threadIdx.x) >> 5;   // node index
    int lane = threadIdx.x & 31;
    if (warp >= BB * NNODE) return;
    const float* hr = g_h + warp * HID;
#pragma unroll
    for (int hh = 0; hh < NH; hh++) {
        float v1 = hr[hh * 64 + lane], v2 = hr[hh * 64 + 32 + lane];
        float s = v1 * asrc[hh * 64 + lane] + v2 * asrc[hh * 64 + 32 + lane];
        float d = v1 * adst[hh * 64 + lane] + v2 * adst[hh * 64 + 32 + lane];
#pragma unroll
        for (int off = 16; off; off >>= 1) {
            s += __shfl_down_sync(0xffffffffu, s, off);
            d += __shfl_down_sync(0xffffffffu, d, off);
        }
        if (lane == 0) {
            int o = warp * NH + hh;
            g_srcv[o] = s;             g_dstv[o] = d;
            g_esp[o] = expf(s);        g_esn[o] = expf(0.2f * s);
            g_edp[o] = expf(d);        g_edn[o] = expf(0.2f * d);
        }
    }
}

// ---------------- GAT aggregation + ELU ----------------
// out[b,i,hh*64+d] = elu( (1/Z) * sum_j e_ij * h[j,hh*64+d] )
// e_ij = adj ? (src_i+dst_j>=0 ? exp(src_i)exp(dst_j) : exp(.2src_i)exp(.2dst_j)) : 0
//
// Phase-2 uses packed fma.rn.f32x2 over ROW-pairs: e-tile is stored
// transposed [head][j][i] (slab padded to 264 floats so phase-1 stores are
// bank-conflict-free: bank = (h*8+i) mod 32, all 32 lanes distinct; slab
// base 1056B stays 16B-aligned for LDS.128 e-pair loads).
#define TI 8
#define TJ 32
#define ESLAB 264   // TJ*TI + 8 pad floats per head slab
__global__ void __launch_bounds__(256) k_agg(const int* __restrict__ adj,
                                             float* __restrict__ outn) {
    __shared__ float hs[TJ][HID];                       // 32 KB
    __shared__ __align__(16) float es2[NH * ESLAB];     // 4.2 KB, [h][j][i]
    __shared__ float zs[TI * NH];

    int b  = blockIdx.x >> 8;              // 256 i-tiles per batch
    int i0 = (blockIdx.x & 255) * TI;
    int tid = threadIdx.x;

    if (tid < TI * NH) zs[tid] = 0.f;

    // phase-1 mapping: lane -> (i, head); j uniform per warp (per rep)
    int i_p1 = tid & 7;
    int h_p1 = (tid >> 3) & 3;
    int jg   = tid >> 5;                   // 0..7; j = jg + 8*rep

    int oi = (b * NNODE + i0 + i_p1) * NH + h_p1;
    float s_src = g_srcv[oi];
    float s_ep  = g_esp[oi];
    float s_en  = g_esn[oi];
    const int* arow = adj + b * NNODE * NNODE + (i0 + i_p1) * NNODE;
    float zloc = 0.f;

    // phase-2 mapping: column = tid, head = tid>>6
    int hh = tid >> 6;
    const float* eslab = es2 + hh * ESLAB;

    unsigned long long acc2[4] = {0ull, 0ull, 0ull, 0ull};  // row-pairs (0,1)(2,3)(4,5)(6,7)

    for (int jt = 0; jt < NNODE / TJ; jt++) {
        int j0 = jt * TJ;
        __syncthreads();
        // load h tile (32 rows x 256 f32) as float4
        {
            const float4* s4 = (const float4*)(g_h + (b * NNODE + j0) * HID);
            float4* d4 = (float4*)hs;
#pragma unroll
            for (int k = 0; k < 8; k++) d4[tid + k * 256] = s4[tid + k * 256];
        }
        // phase 1: compute e for (i_p1, j, h_p1), j = jg + 8*rep
#pragma unroll
        for (int rep = 0; rep < 4; rep++) {
            int j = jg + 8 * rep;
            int oj = (b * NNODE + j0 + j) * NH + h_p1;
            float dv  = g_dstv[oj];
            float dep = g_edp[oj];
            float den = g_edn[oj];
            int a = arow[j0 + j];
            float sv = s_src + dv;
            float e = 0.f;
            if (a > 0) e = (sv >= 0.f) ? s_ep * dep : s_en * den;
            es2[h_p1 * ESLAB + j * 8 + i_p1] = e;
            zloc += e;
        }
        __syncthreads();
        // phase 2: acc[row-pair] += e2 * {hv,hv}
#pragma unroll 4
        for (int j = 0; j < TJ; j++) {
            unsigned long long hv2 = pack2(hs[j][tid]);
            ulonglong2 ea = *(const ulonglong2*)(eslab + j * 8);      // rows (0,1),(2,3)
            ulonglong2 eb = *(const ulonglong2*)(eslab + j * 8 + 4);  // rows (4,5),(6,7)
            acc2[0] = fma2(ea.x, hv2, acc2[0]);
            acc2[1] = fma2(ea.y, hv2, acc2[1]);
            acc2[2] = fma2(eb.x, hv2, acc2[2]);
            acc2[3] = fma2(eb.y, hv2, acc2[3]);
        }
    }
    // reduce Z: one atomic per thread (8 threads per (i,h) slot)
    atomicAdd(&zs[i_p1 * NH + h_p1], zloc);
    __syncthreads();
    // epilogue: normalize + ELU, write node output
#pragma unroll
    for (int r = 0; r < 4; r++) {
        float v0, v1;
        unpack2(acc2[r], v0, v1);
        int ia = 2 * r, ib = 2 * r + 1;
        float r0 = v0 / zs[ia * NH + hh];
        float r1 = v1 / zs[ib * NH + hh];
        outn[(b * NNODE + i0 + ia) * HID + tid] = (r0 > 0.f) ? r0 : expm1f(r0);
        outn[(b * NNODE + i0 + ib) * HID + tid] = (r1 > 0.f) ? r1 : expm1f(r1);
    }
}

// ---------------- host orchestration ----------------
static void run_pool(const float* x, const float* w1, const float* b1,
                     const float* w2, float* outp) {
    k_pool_score<<<BB * NNODE / 8, 128>>>(x, w1, b1, w2);
    k_pool_a<<<BB, 256>>>();
    k_pool_b<<<BB * 16, 256>>>(x);
    k_pool_c<<<BB, 256>>>(outp);
}

extern "C" void kernel_launch(void* const* d_in, const int* in_sizes, int n_in,
                              void* d_out, int out_size) {
    const float* ge       = (const float*)d_in[0];
    const int*   adj      = (const int*)  d_in[1];
    const float* in_w     = (const float*)d_in[2];
    const float* in_b     = (const float*)d_in[3];
    const float* proj_w   = (const float*)d_in[4];   // [2,256,256]
    const float* attn_src = (const float*)d_in[5];   // [2,4,64]
    const float* attn_dst = (const float*)d_in[6];
    const float* pool_w1  = (const float*)d_in[7];   // [2,256,128]
    const float* pool_b1  = (const float*)d_in[8];   // [2,128]
    const float* pool_w2  = (const float*)d_in[9];   // [2,128]
    const float* ip_w1    = (const float*)d_in[11];  // [256,128]
    const float* ip_b1    = (const float*)d_in[12];
    const float* ip_w2    = (const float*)d_in[13];

    float* out = (float*)d_out;
    const int NODE_SZ = BB * NNODE * HID;            // 1048576
    float* raw_pooled = out;
    float* node0 = out + BB * HID;
    float* node1 = node0 + NODE_SZ;
    float* pooled0 = node1 + NODE_SZ;
    float* pooled1 = pooled0 + BB * HID;

    float* x0 = nullptr;
    cudaGetSymbolAddress((void**)&x0, g_x0);

    // input projection
    k_input<<<BB * NNODE * HID / 256, 256>>>(ge, in_w, in_b);

    // raw pooled (on x0)
    run_pool(x0, ip_w1, ip_b1, ip_w2, raw_pooled);

    // layer 0
    k_gemm<<<BB * NNODE / 16, 256>>>(x0, proj_w);
    k_srcdst<<<BB * NNODE / 8, 256>>>(attn_src, attn_dst);
    k_agg<<<BB * (NNODE / TI), 256>>>(adj, node0);
    run_pool(node0, pool_w1, pool_b1, pool_w2, pooled0);

    // layer 1
    k_gemm<<<BB * NNODE / 16, 256>>>(node0, proj_w + HID * HID);
    k_srcdst<<<BB * NNODE / 8, 256>>>(attn_src + NH * DD, attn_dst + NH * DD);
    k_agg<<<BB * (NNODE / TI), 256>>>(adj, node1);
    run_pool(node1, pool_w1 + HID * PL, pool_b1 + PL, pool_w2 + PL, pooled1);
}

// round 7
// speedup vs baseline: 1.0652x; 1.0652x over previous
#include <cuda_runtime.h>
#include <math.h>

#define BB   2
#define NNODE 2048
#define HID  256
#define NH   4
#define DD   64
#define PL   128

// ---------------- scratch (device globals; no allocation allowed) ----------------
__device__ float g_x0[BB*NNODE*HID];       // input-proj output (4 MB)
__device__ float g_h[BB*NNODE*HID];        // per-layer projected features (4 MB)
__device__ float4 g_spk[BB*NNODE*NH];      // (src, exp(src), exp(.2src), 0)
__device__ float4 g_dpk[BB*NNODE*NH];      // (dst, exp(dst), exp(.2dst), 0)
__device__ float g_pe[BB*NNODE];           // pool exp(score)
__device__ float g_partial[BB*128*HID];    // pool partial weighted sums

// ---------------- packed f32x2 helpers (sm_103a) ----------------
__device__ __forceinline__ unsigned long long pack2(float v) {
    unsigned long long r;
    asm("mov.b64 %0, {%1, %1};" : "=l"(r) : "f"(v));
    return r;
}
__device__ __forceinline__ void unpack2(unsigned long long v, float& lo, float& hi) {
    asm("mov.b64 {%0, %1}, %2;" : "=f"(lo), "=f"(hi) : "l"(v));
}
__device__ __forceinline__ unsigned long long fma2(unsigned long long a,
                                                   unsigned long long b,
                                                   unsigned long long c) {
    unsigned long long d;
    asm("fma.rn.f32x2 %0, %1, %2, %3;" : "=l"(d) : "l"(a), "l"(b), "l"(c));
    return d;
}
__device__ __forceinline__ unsigned int smem_u32(const void* p) {
    unsigned int a;
    asm("{ .reg .u64 t; cvta.to.shared.u64 t, %1; cvt.u32.u64 %0, t; }"
        : "=r"(a) : "l"(p));
    return a;
}

// ---------------- input projection: x = relu(ge * w + b) ----------------
__global__ void k_input(const float* __restrict__ ge,
                        const float* __restrict__ w,
                        const float* __restrict__ b) {
    int idx = blockIdx.x * 256 + threadIdx.x;   // over B*N*HID
    int c = idx & (HID - 1);
    float v = fmaf(ge[idx >> 8], w[c], b[c]);
    g_x0[idx] = v > 0.f ? v : 0.f;
}

// ---------------- attn-pool score -> exp(score) directly ----------------
// s[n] = sum_p tanh(x@w1 + b1)_p * w2_p ; b2 omitted (softmax shift-invariant);
// |s| <= sum|w2| ~ 5, so exp without max-subtraction is safe in f32.
__global__ void k_pool_score(const float* __restrict__ x,
                             const float* __restrict__ w1,
                             const float* __restrict__ b1,
                             const float* __restrict__ w2) {
    __shared__ float xs[8][HID];
    __shared__ float red[4][8];
    int row0 = blockIdx.x * 8;
    int tid = threadIdx.x;   // 128 threads
    const float4* s4 = (const float4*)(x + row0 * HID);
    float4* d4 = (float4*)xs;
#pragma unroll
    for (int k = 0; k < 4; k++) d4[tid + k * 128] = s4[tid + k * 128];
    __syncthreads();

    float acc[8];
#pragma unroll
    for (int r = 0; r < 8; r++) acc[r] = 0.f;
    for (int c = 0; c < HID; c++) {
        float wv = w1[c * PL + tid];
#pragma unroll
        for (int r = 0; r < 8; r++) acc[r] = fmaf(xs[r][c], wv, acc[r]);
    }
    float bv = b1[tid], w2v = w2[tid];
    int lane = tid & 31, wp = tid >> 5;
#pragma unroll
    for (int r = 0; r < 8; r++) {
        float v = tanhf(acc[r] + bv) * w2v;
#pragma unroll
        for (int off = 16; off; off >>= 1) v += __shfl_down_sync(0xffffffffu, v, off);
        if (lane == 0) red[wp][r] = v;
    }
    __syncthreads();
    if (tid < 8)
        g_pe[row0 + tid] = expf(red[0][tid] + red[1][tid] + red[2][tid] + red[3][tid]);
}

// ---------------- pool weighted partial sums: 128 segments of 16 nodes ----------------
__global__ void k_pool_b(const float* __restrict__ x) {
    int b = blockIdx.x >> 7, seg = blockIdx.x & 127;
    int c = threadIdx.x;
    int n0 = seg * 16;
    float acc = 0.f;
#pragma unroll
    for (int k = 0; k < 16; k++) {
        int n = n0 + k;
        acc = fmaf(g_pe[b * NNODE + n], x[(b * NNODE + n) * HID + c], acc);
    }
    g_partial[blockIdx.x * HID + c] = acc;
}

// ---------------- pool finalize: reduce 128 partials, compute Z inline ----------------
__global__ void k_pool_c(float* __restrict__ outp) {
    __shared__ float red[256];
    int b = blockIdx.x, c = threadIdx.x;
    float z = 0.f;
    for (int n = c; n < NNODE; n += 256) z += g_pe[b * NNODE + n];
    red[c] = z; __syncthreads();
    for (int s = 128; s > 0; s >>= 1) { if (c < s) red[c] += red[c + s]; __syncthreads(); }
    z = red[0];
    float acc = 0.f;
#pragma unroll 4
    for (int seg = 0; seg < 128; seg++) acc += g_partial[(b * 128 + seg) * HID + c];
    outp[b * HID + c] = acc / z;
}

// ---------------- h = cur @ W (4096x256 @ 256x256) ----------------
__global__ void k_gemm(const float* __restrict__ xin, const float* __restrict__ W) {
    __shared__ float xs[16][HID];
    int row0 = blockIdx.x * 16;
    int tid = threadIdx.x;   // 256 = output column
    const float4* s4 = (const float4*)(xin + row0 * HID);
    float4* d4 = (float4*)xs;
#pragma unroll
    for (int k = 0; k < 4; k++) d4[tid + k * 256] = s4[tid + k * 256];
    __syncthreads();

    float acc[16];
#pragma unroll
    for (int r = 0; r < 16; r++) acc[r] = 0.f;
    for (int c = 0; c < HID; c += 4) {
        float w0 = W[(c + 0) * HID + tid];
        float w1 = W[(c + 1) * HID + tid];
        float w2 = W[(c + 2) * HID + tid];
        float w3 = W[(c + 3) * HID + tid];
#pragma unroll
        for (int r = 0; r < 16; r++) {
            float4 xv = *(const float4*)&xs[r][c];
            acc[r] = fmaf(xv.x, w0, acc[r]);
            acc[r] = fmaf(xv.y, w1, acc[r]);
            acc[r] = fmaf(xv.z, w2, acc[r]);
            acc[r] = fmaf(xv.w, w3, acc[r]);
        }
    }
#pragma unroll
    for (int r = 0; r < 16; r++) g_h[(row0 + r) * HID + tid] = acc[r];
}

// ---------------- src/dst projections + packed exp tables ----------------
__global__ void k_srcdst(const float* __restrict__ asrc, const float* __restrict__ adst) {
    int warp = (blockIdx.x * blockDim.x + threadIdx.x) >> 5;   // node index
    int lane = threadIdx.x & 31;
    if (warp >= BB * NNODE) return;
    const float* hr = g_h + warp * HID;
#pragma unroll
    for (int hh = 0; hh < NH; hh++) {
        float v1 = hr[hh * 64 + lane], v2 = hr[hh * 64 + 32 + lane];
        float s = v1 * asrc[hh * 64 + lane] + v2 * asrc[hh * 64 + 32 + lane];
        float d = v1 * adst[hh * 64 + lane] + v2 * adst[hh * 64 + 32 + lane];
#pragma unroll
        for (int off = 16; off; off >>= 1) {
            s += __shfl_down_sync(0xffffffffu, s, off);
            d += __shfl_down_sync(0xffffffffu, d, off);
        }
        if (lane == 0) {
            int o = warp * NH + hh;
            g_spk[o] = make_float4(s, expf(s), expf(0.2f * s), 0.f);
            g_dpk[o] = make_float4(d, expf(d), expf(0.2f * d), 0.f);
        }
    }
}

// ---------------- GAT aggregation + ELU ----------------
// out[b,i,hh*64+d] = elu( (1/Z) * sum_j e_ij * h[j,hh*64+d] )
// e_ij = adj ? (src_i+dst_j>=0 ? exp(src_i)exp(dst_j) : exp(.2src_i)exp(.2dst_j)) : 0
//
// TI=16: halves redundant h traffic vs TI=8. e-tile transposed [head][j][i],
// slab 528 floats (bank-conflict-free stores, 16B-aligned LDS.128 pair loads).
// h-tile fill via cp.async (LDGSTS): issued before phase-1, waited after it,
// so the L2/DRAM tile latency overlaps the e-computation instead of stalling
// the warp on LDG->STS register dependencies.
#define TI 16
#define TJ 32
#define ESLAB 528   // TJ*TI + 16 pad floats per head slab
__global__ void __launch_bounds__(256) k_agg(const int* __restrict__ adj,
                                             float* __restrict__ outn) {
    __shared__ __align__(16) float hs[TJ][HID];         // 32 KB
    __shared__ __align__(16) float es2[NH * ESLAB];     // 8.25 KB, [h][j][i]
    __shared__ float zs[TI * NH];                       // 64

    int b  = blockIdx.x >> 7;              // 128 i-tiles per batch
    int i0 = (blockIdx.x & 127) * TI;
    int tid = threadIdx.x;

    if (tid < TI * NH) zs[tid] = 0.f;

    // phase-1 mapping: i_p1 = tid&15, h_p1 = (tid>>4)&3, jg = tid>>6 (0..3)
    int i_p1 = tid & 15;
    int h_p1 = (tid >> 4) & 3;
    int jg   = tid >> 6;                   // j = jg*8 + rep, rep 0..7

    float4 sq = g_spk[(b * NNODE + i0 + i_p1) * NH + h_p1];   // (src, e+, e-)
    const int* __restrict__ arow = adj + b * NNODE * NNODE + (i0 + i_p1) * NNODE + jg * 8;
    const float4* __restrict__ dtab = g_dpk + (b * NNODE) * NH + jg * 8 * NH + h_p1;
    float* __restrict__ eout = es2 + h_p1 * ESLAB + jg * 8 * 16 + i_p1;
    float zloc = 0.f;

    // phase-2 mapping: column = tid, head = tid>>6
    int hh = tid >> 6;
    const float* eslab = es2 + hh * ESLAB;

    // cp.async addressing: this thread fills 8 x 16B of the h tile
    unsigned int hs_dst = smem_u32(hs) + (unsigned int)tid * 16u;
    const float4* hsrc_base = (const float4*)(g_h + b * NNODE * HID) + tid;

    unsigned long long acc2[8];            // row-pairs (0,1)...(14,15)
#pragma unroll
    for (int r = 0; r < 8; r++) acc2[r] = 0ull;

    for (int jt = 0; jt < NNODE / TJ; jt++) {
        int j0 = jt * TJ;
        __syncthreads();   // prior phase-2 done with hs and es2
        // issue async h-tile fill (32 rows x 256 f32); overlaps with phase 1
        {
            const float4* src = hsrc_base + j0 * (HID / 4);
#pragma unroll
            for (int k = 0; k < 8; k++)
                asm volatile("cp.async.cg.shared.global [%0], [%1], 16;"
                             :: "r"(hs_dst + k * 4096u), "l"(src + k * 256) : "memory");
            asm volatile("cp.async.commit_group;" ::: "memory");
        }
        // phase 1: e for (i_p1, j = jg*8+rep, h_p1); adj as 2x int4
        {
            const int4* a4 = (const int4*)(arow + j0);
            int4 aa = a4[0], ab = a4[1];
            int av[8] = {aa.x, aa.y, aa.z, aa.w, ab.x, ab.y, ab.z, ab.w};
            const float4* dq4 = dtab + j0 * NH;
#pragma unroll
            for (int rep = 0; rep < 8; rep++) {
                float4 dq = dq4[rep * NH];
                float sv = sq.x + dq.x;
                float e = 0.f;
                if (av[rep] > 0) e = (sv >= 0.f) ? sq.y * dq.y : sq.z * dq.z;
                eout[rep * 16] = e;
                zloc += e;
            }
        }
        asm volatile("cp.async.wait_group 0;" ::: "memory");
        __syncthreads();   // hs filled + es2 visible
        // phase 2: acc[row-pair] += e2 * {hv,hv}
#pragma unroll 8
        for (int j = 0; j < TJ; j++) {
            unsigned long long hv2 = pack2(hs[j][tid]);
            const ulonglong2* ep = (const ulonglong2*)(eslab + j * 16);
            ulonglong2 e0 = ep[0];   // rows (0,1),(2,3)
            ulonglong2 e1 = ep[1];   // rows (4,5),(6,7)
            ulonglong2 e2 = ep[2];   // rows (8,9),(10,11)
            ulonglong2 e3 = ep[3];   // rows (12,13),(14,15)
            acc2[0] = fma2(e0.x, hv2, acc2[0]);
            acc2[1] = fma2(e0.y, hv2, acc2[1]);
            acc2[2] = fma2(e1.x, hv2, acc2[2]);
            acc2[3] = fma2(e1.y, hv2, acc2[3]);
            acc2[4] = fma2(e2.x, hv2, acc2[4]);
            acc2[5] = fma2(e2.y, hv2, acc2[5]);
            acc2[6] = fma2(e3.x, hv2, acc2[6]);
            acc2[7] = fma2(e3.y, hv2, acc2[7]);
        }
    }
    // reduce Z: one atomic per thread (4 jg threads per (i,h) slot)
    atomicAdd(&zs[i_p1 * NH + h_p1], zloc);
    __syncthreads();
    // epilogue: normalize + ELU, write node output
#pragma unroll
    for (int r = 0; r < 8; r++) {
        float v0, v1;
        unpack2(acc2[r], v0, v1);
        int ia = 2 * r, ib = 2 * r + 1;
        float r0 = v0 / zs[ia * NH + hh];
        float r1 = v1 / zs[ib * NH + hh];
        outn[(b * NNODE + i0 + ia) * HID + tid] = (r0 > 0.f) ? r0 : expm1f(r0);
        outn[(b * NNODE + i0 + ib) * HID + tid] = (r1 > 0.f) ? r1 : expm1f(r1);
    }
}

// ---------------- host orchestration ----------------
static void run_pool(const float* x, const float* w1, const float* b1,
                     const float* w2, float* outp) {
    k_pool_score<<<BB * NNODE / 8, 128>>>(x, w1, b1, w2);
    k_pool_b<<<BB * 128, 256>>>(x);
    k_pool_c<<<BB, 256>>>(outp);
}

extern "C" void kernel_launch(void* const* d_in, const int* in_sizes, int n_in,
                              void* d_out, int out_size) {
    const float* ge       = (const float*)d_in[0];
    const int*   adj      = (const int*)  d_in[1];
    const float* in_w     = (const float*)d_in[2];
    const float* in_b     = (const float*)d_in[3];
    const float* proj_w   = (const float*)d_in[4];   // [2,256,256]
    const float* attn_src = (const float*)d_in[5];   // [2,4,64]
    const float* attn_dst = (const float*)d_in[6];
    const float* pool_w1  = (const float*)d_in[7];   // [2,256,128]
    const float* pool_b1  = (const float*)d_in[8];   // [2,128]
    const float* pool_w2  = (const float*)d_in[9];   // [2,128]
    const float* ip_w1    = (const float*)d_in[11];  // [256,128]
    const float* ip_b1    = (const float*)d_in[12];
    const float* ip_w2    = (const float*)d_in[13];

    float* out = (float*)d_out;
    const int NODE_SZ = BB * NNODE * HID;            // 1048576
    float* raw_pooled = out;
    float* node0 = out + BB * HID;
    float* node1 = node0 + NODE_SZ;
    float* pooled0 = node1 + NODE_SZ;
    float* pooled1 = pooled0 + BB * HID;

    float* x0 = nullptr;
    cudaGetSymbolAddress((void**)&x0, g_x0);

    // input projection
    k_input<<<BB * NNODE * HID / 256, 256>>>(ge, in_w, in_b);

    // raw pooled (on x0)
    run_pool(x0, ip_w1, ip_b1, ip_w2, raw_pooled);

    // layer 0
    k_gemm<<<BB * NNODE / 16, 256>>>(x0, proj_w);
    k_srcdst<<<BB * NNODE / 8, 256>>>(attn_src, attn_dst);
    k_agg<<<BB * (NNODE / TI), 256>>>(adj, node0);
    run_pool(node0, pool_w1, pool_b1, pool_w2, pooled0);

    // layer 1
    k_gemm<<<BB * NNODE / 16, 256>>>(node0, proj_w + HID * HID);
    k_srcdst<<<BB * NNODE / 8, 256>>>(attn_src + NH * DD, attn_dst + NH * DD);
    k_agg<<<BB * (NNODE / TI), 256>>>(adj, node1);
    run_pool(node1, pool_w1 + HID * PL, pool_b1 + PL, pool_w2 + PL, pooled1);
}

// round 10
// speedup vs baseline: 1.0782x; 1.0122x over previous
#include <cuda_runtime.h>
#include <math.h>

#define BB   2
#define NNODE 2048
#define HID  256
#define NH   4
#define DD   64
#define PL   128

// ---------------- scratch (device globals; no allocation allowed) ----------------
__device__ float g_x0[BB*NNODE*HID];       // input-proj output (4 MB)
__device__ float g_h[BB*NNODE*HID];        // per-layer projected features (4 MB)
__device__ float4 g_spk[BB*NNODE*NH];      // (src, exp(src), exp(.2src), 0)
__device__ float4 g_dpk[BB*NNODE*NH];      // (dst, exp(dst), exp(.2dst), 0)
__device__ float g_partial[BB*128*HID];    // pool partial weighted sums (unnormalized)
__device__ float g_zpart[BB*128];          // pool partial Z

// ---------------- packed f32x2 helpers (sm_103a) ----------------
__device__ __forceinline__ unsigned long long pack2(float v) {
    unsigned long long r;
    asm("mov.b64 %0, {%1, %1};" : "=l"(r) : "f"(v));
    return r;
}
__device__ __forceinline__ void unpack2(unsigned long long v, float& lo, float& hi) {
    asm("mov.b64 {%0, %1}, %2;" : "=f"(lo), "=f"(hi) : "l"(v));
}
__device__ __forceinline__ unsigned long long fma2(unsigned long long a,
                                                   unsigned long long b,
                                                   unsigned long long c) {
    unsigned long long d;
    asm("fma.rn.f32x2 %0, %1, %2, %3;" : "=l"(d) : "l"(a), "l"(b), "l"(c));
    return d;
}
__device__ __forceinline__ unsigned int smem_u32(const void* p) {
    unsigned int a;
    asm("{ .reg .u64 t; cvta.to.shared.u64 t, %1; cvt.u32.u64 %0, t; }"
        : "=r"(a) : "l"(p));
    return a;
}

// ---------------- input projection: x = relu(ge * w + b) ----------------
__global__ void k_input(const float* __restrict__ ge,
                        const float* __restrict__ w,
                        const float* __restrict__ b) {
    int idx = blockIdx.x * 256 + threadIdx.x;   // over B*N*HID
    int c = idx & (HID - 1);
    float v = fmaf(ge[idx >> 8], w[c], b[c]);
    g_x0[idx] = v > 0.f ? v : 0.f;
}

// ---------------- fused pool: scores -> exp -> weighted partial + Z partial ----
// Block = 16 nodes. s[n] = sum_p tanh(x@w1+b1)_p * w2_p (b2 dropped: shift-inv).
// |s| small => exp without max-subtraction is safe in f32.
__global__ void __launch_bounds__(256) k_pool_sb(const float* __restrict__ x,
                                                 const float* __restrict__ w1,
                                                 const float* __restrict__ b1,
                                                 const float* __restrict__ w2) {
    __shared__ float xs[16][HID];      // 16 KB
    __shared__ float red[16][4];
    __shared__ float se[16];
    int b = blockIdx.x >> 7, seg = blockIdx.x & 127;
    int tid = threadIdx.x;
    long n0 = (long)b * NNODE + seg * 16;

    // load 16 rows (1024 float4)
    const float4* s4 = (const float4*)(x + n0 * HID);
    float4* d4 = (float4*)xs;
#pragma unroll
    for (int k = 0; k < 4; k++) d4[tid + k * 256] = s4[tid + k * 256];
    __syncthreads();

    // scores: half = tid>>7 handles rows half*8..+7 with 128 threads (p = tid&127)
    int half = tid >> 7, p = tid & 127;
    float acc[8];
#pragma unroll
    for (int r = 0; r < 8; r++) acc[r] = 0.f;
    for (int c = 0; c < HID; c++) {
        float wv = w1[c * PL + p];
#pragma unroll
        for (int r = 0; r < 8; r++) acc[r] = fmaf(xs[half * 8 + r][c], wv, acc[r]);
    }
    float bv = b1[p], w2v = w2[p];
    int lane = tid & 31, wp = tid >> 5;    // global warp 0..7; within-half warp = wp&3
#pragma unroll
    for (int r = 0; r < 8; r++) {
        float v = tanhf(acc[r] + bv) * w2v;
#pragma unroll
        for (int off = 16; off; off >>= 1) v += __shfl_down_sync(0xffffffffu, v, off);
        if (lane == 0) red[half * 8 + r][wp & 3] = v;
    }
    __syncthreads();
    if (tid < 16) {
        float s = red[tid][0] + red[tid][1] + red[tid][2] + red[tid][3];
        float e = expf(s);
        se[tid] = e;
        float z = e;
#pragma unroll
        for (int off = 8; off; off >>= 1) z += __shfl_down_sync(0x0000ffffu, z, off, 16);
        if (tid == 0) g_zpart[b * 128 + seg] = z;
    }
    __syncthreads();
    // weighted partial for this segment: acc over 16 rows, column = tid
    float a = 0.f;
#pragma unroll
    for (int r = 0; r < 16; r++) a = fmaf(se[r], xs[r][tid], a);
    g_partial[(b * 128 + seg) * HID + tid] = a;
}

// ---------------- pool finalize: parallel reduce 128 partials + Z, divide ------
__global__ void k_pool_c2(float* __restrict__ outp) {
    __shared__ float chunks[4][64];
    __shared__ float zred[2];
    int b = blockIdx.x >> 2, cg = blockIdx.x & 3;
    int tid = threadIdx.x;
    int c = cg * 64 + (tid & 63), sc = tid >> 6;
    float a = 0.f;
#pragma unroll 8
    for (int k = 0; k < 32; k++)
        a += g_partial[(b * 128 + sc * 32 + k) * HID + c];
    chunks[sc][tid & 63] = a;
    // Z reduce by warp 0
    if (tid < 32) {
        float z = g_zpart[b * 128 + tid] + g_zpart[b * 128 + 32 + tid]
                + g_zpart[b * 128 + 64 + tid] + g_zpart[b * 128 + 96 + tid];
#pragma unroll
        for (int off = 16; off; off >>= 1) z += __shfl_down_sync(0xffffffffu, z, off);
        if (tid == 0) zred[0] = z;
    }
    __syncthreads();
    if (tid < 64) {
        float t = chunks[0][tid] + chunks[1][tid] + chunks[2][tid] + chunks[3][tid];
        outp[b * HID + cg * 64 + tid] = t / zred[0];
    }
}

// ---------------- h = cur @ W, fused src/dst projections + exp tables ----------
__global__ void __launch_bounds__(256) k_gemm(const float* __restrict__ xin,
                                              const float* __restrict__ W,
                                              const float* __restrict__ asrc,
                                              const float* __restrict__ adst) {
    __shared__ float xs[16][HID];      // 16 KB
    __shared__ float sred[16][8], dred[16][8];
    int row0 = blockIdx.x * 16;
    int tid = threadIdx.x;   // 256 = output column
    const float4* s4 = (const float4*)(xin + row0 * HID);
    float4* d4 = (float4*)xs;
#pragma unroll
    for (int k = 0; k < 4; k++) d4[tid + k * 256] = s4[tid + k * 256];
    __syncthreads();

    float acc[16];
#pragma unroll
    for (int r = 0; r < 16; r++) acc[r] = 0.f;
    for (int c = 0; c < HID; c += 4) {
        float w0 = W[(c + 0) * HID + tid];
        float w1 = W[(c + 1) * HID + tid];
        float w2 = W[(c + 2) * HID + tid];
        float w3 = W[(c + 3) * HID + tid];
#pragma unroll
        for (int r = 0; r < 16; r++) {
            float4 xv = *(const float4*)&xs[r][c];
            acc[r] = fmaf(xv.x, w0, acc[r]);
            acc[r] = fmaf(xv.y, w1, acc[r]);
            acc[r] = fmaf(xv.z, w2, acc[r]);
            acc[r] = fmaf(xv.w, w3, acc[r]);
        }
    }
#pragma unroll
    for (int r = 0; r < 16; r++) g_h[(row0 + r) * HID + tid] = acc[r];

    // src/dst epilogue: head = col>>6; reduce acc[r]*a over each 64-col head segment
    float as = asrc[tid], ad = adst[tid];
    int lane = tid & 31, wp = tid >> 5;     // warps 2h, 2h+1 cover head h
#pragma unroll
    for (int r = 0; r < 16; r++) {
        float vs = acc[r] * as, vd = acc[r] * ad;
#pragma unroll
        for (int off = 16; off; off >>= 1) {
            vs += __shfl_down_sync(0xffffffffu, vs, off);
            vd += __shfl_down_sync(0xffffffffu, vd, off);
        }
        if (lane == 0) { sred[r][wp] = vs; dred[r][wp] = vd; }
    }
    __syncthreads();
    if (tid < 64) {
        int r = tid & 15, hh = tid >> 4;
        float s = sred[r][2 * hh] + sred[r][2 * hh + 1];
        float d = dred[r][2 * hh] + dred[r][2 * hh + 1];
        int o = (row0 + r) * NH + hh;
        g_spk[o] = make_float4(s, expf(s), expf(0.2f * s), 0.f);
        g_dpk[o] = make_float4(d, expf(d), expf(0.2f * d), 0.f);
    }
}

// ---------------- GAT aggregation + ELU ----------------
// out[b,i,hh*64+d] = elu( (1/Z) * sum_j e_ij * h[j,hh*64+d] )
// e_ij = adj ? (src_i+dst_j>=0 ? exp(src_i)exp(dst_j) : exp(.2src_i)exp(.2dst_j)) : 0
//
// TI=16, TJ=16, DOUBLE-BUFFERED h-tiles: tile jt+1's cp.async is issued right
// after the loop-top sync, so it has phase-1 + the previous phase-2 to land.
// wait_group 1 keeps exactly one group in flight. e-tile transposed [h][j][i],
// slab 272 floats: store banks (h*16 + 16(j&1) + i) mod 32 all-distinct per warp;
// slab base 1088 B is 16B-aligned for LDS.128 row-pair loads.
#define TI 16
#define TJ 16
#define ESLAB 272   // TJ*TI + 16 pad floats per head slab
__global__ void __launch_bounds__(256) k_agg(const int* __restrict__ adj,
                                             float* __restrict__ outn) {
    __shared__ __align__(16) float hs[2][TJ][HID];      // 32 KB (double buffer)
    __shared__ __align__(16) float es2[NH * ESLAB];     // 4.25 KB, [h][j][i]
    __shared__ float zs[TI * NH];                       // 64

    int b  = blockIdx.x >> 7;              // 128 i-tiles per batch
    int i0 = (blockIdx.x & 127) * TI;
    int tid = threadIdx.x;

    if (tid < TI * NH) zs[tid] = 0.f;

    // phase-1 mapping: i_p1 = tid&15, h_p1 = (tid>>4)&3, jg = tid>>6 (0..3)
    int i_p1 = tid & 15;
    int h_p1 = (tid >> 4) & 3;
    int jg   = tid >> 6;                   // j = jg*4 + rep, rep 0..3

    float4 sq = g_spk[(b * NNODE + i0 + i_p1) * NH + h_p1];   // (src, e+, e-)
    const int* __restrict__ arow = adj + b * NNODE * NNODE + (i0 + i_p1) * NNODE + jg * 4;
    const float4* __restrict__ dtab = g_dpk + (b * NNODE) * NH + jg * 4 * NH + h_p1;
    float* __restrict__ eout = es2 + h_p1 * ESLAB + jg * 4 * 16 + i_p1;
    float zloc = 0.f;

    // phase-2 mapping: column = tid, head = tid>>6
    int hh = tid >> 6;
    const float* eslab = es2 + hh * ESLAB;

    // cp.async addressing: each thread fills 4 x 16B per tile buffer
    unsigned int hs0 = smem_u32(hs) + (unsigned int)tid * 16u;
    const float4* hsrc_base = (const float4*)(g_h + b * NNODE * HID) + tid;

    unsigned long long acc2[8];            // row-pairs (0,1)...(14,15)
#pragma unroll
    for (int r = 0; r < 8; r++) acc2[r] = 0ull;

    // prologue: issue tile 0 into buffer 0
    {
        const float4* src = hsrc_base;
#pragma unroll
        for (int k = 0; k < 4; k++)
            asm volatile("cp.async.cg.shared.global [%0], [%1], 16;"
                         :: "r"(hs0 + k * 4096u), "l"(src + k * 256) : "memory");
        asm volatile("cp.async.commit_group;" ::: "memory");
    }

    const int NT = NNODE / TJ;   // 128 tiles
    for (int jt = 0; jt < NT; jt++) {
        int j0 = jt * TJ;
        int cur = jt & 1;
        __syncthreads();   // phase2(jt-1) done: es2 free, buf cur^1 free
        // issue next tile into the other buffer
        if (jt + 1 < NT) {
            const float4* src = hsrc_base + (j0 + TJ) * (HID / 4);
            unsigned int dst = hs0 + (unsigned int)(cur ^ 1) * 16384u;
#pragma unroll
            for (int k = 0; k < 4; k++)
                asm volatile("cp.async.cg.shared.global [%0], [%1], 16;"
                             :: "r"(dst + k * 4096u), "l"(src + k * 256) : "memory");
            asm volatile("cp.async.commit_group;" ::: "memory");
        }
        // phase 1: e for (i_p1, j = jg*4+rep, h_p1); adj as int4
        {
            int4 aa = *(const int4*)(arow + j0);
            int av[4] = {aa.x, aa.y, aa.z, aa.w};
            const float4* dq4 = dtab + j0 * NH;
#pragma unroll
            for (int rep = 0; rep < 4; rep++) {
                float4 dq = dq4[rep * NH];
                float sv = sq.x + dq.x;
                float e = 0.f;
                if (av[rep] > 0) e = (sv >= 0.f) ? sq.y * dq.y : sq.z * dq.z;
                eout[rep * 16] = e;
                zloc += e;
            }
        }
        // wait for THIS tile's data (1 newer group may stay in flight)
        if (jt + 1 < NT) asm volatile("cp.async.wait_group 1;" ::: "memory");
        else             asm volatile("cp.async.wait_group 0;" ::: "memory");
        __syncthreads();   // hs[cur] filled + es2 visible
        // phase 2: acc[row-pair] += e2 * {hv,hv}
#pragma unroll 8
        for (int j = 0; j < TJ; j++) {
            unsigned long long hv2 = pack2(hs[cur][j][tid]);
            const ulonglong2* ep = (const ulonglong2*)(eslab + j * 16);
            ulonglong2 e0 = ep[0];   // rows (0,1),(2,3)
            ulonglong2 e1 = ep[1];   // rows (4,5),(6,7)
            ulonglong2 e2 = ep[2];   // rows (8,9),(10,11)
            ulonglong2 e3 = ep[3];   // rows (12,13),(14,15)
            acc2[0] = fma2(e0.x, hv2, acc2[0]);
            acc2[1] = fma2(e0.y, hv2, acc2[1]);
            acc2[2] = fma2(e1.x, hv2, acc2[2]);
            acc2[3] = fma2(e1.y, hv2, acc2[3]);
            acc2[4] = fma2(e2.x, hv2, acc2[4]);
            acc2[5] = fma2(e2.y, hv2, acc2[5]);
            acc2[6] = fma2(e3.x, hv2, acc2[6]);
            acc2[7] = fma2(e3.y, hv2, acc2[7]);
        }
    }
    // reduce Z: one atomic per thread (4 jg threads per (i,h) slot)
    atomicAdd(&zs[i_p1 * NH + h_p1], zloc);
    __syncthreads();
    // epilogue: normalize + ELU, write node output
#pragma unroll
    for (int r = 0; r < 8; r++) {
        float v0, v1;
        unpack2(acc2[r], v0, v1);
        int ia = 2 * r, ib = 2 * r + 1;
        float r0 = v0 / zs[ia * NH + hh];
        float r1 = v1 / zs[ib * NH + hh];
        outn[(b * NNODE + i0 + ia) * HID + tid] = (r0 > 0.f) ? r0 : expm1f(r0);
        outn[(b * NNODE + i0 + ib) * HID + tid] = (r1 > 0.f) ? r1 : expm1f(r1);
    }
}

// ---------------- host orchestration ----------------
static void run_pool(const float* x, const float* w1, const float* b1,
                     const float* w2, float* outp) {
    k_pool_sb<<<BB * 128, 256>>>(x, w1, b1, w2);
    k_pool_c2<<<BB * 4, 256>>>(outp);
}

extern "C" void kernel_launch(void* const* d_in, const int* in_sizes, int n_in,
                              void* d_out, int out_size) {
    const float* ge       = (const float*)d_in[0];
    const int*   adj      = (const int*)  d_in[1];
    const float* in_w     = (const float*)d_in[2];
    const float* in_b     = (const float*)d_in[3];
    const float* proj_w   = (const float*)d_in[4];   // [2,256,256]
    const float* attn_src = (const float*)d_in[5];   // [2,4,64]
    const float* attn_dst = (const float*)d_in[6];
    const float* pool_w1  = (const float*)d_in[7];   // [2,256,128]
    const float* pool_b1  = (const float*)d_in[8];   // [2,128]
    const float* pool_w2  = (const float*)d_in[9];   // [2,128]
    const float* ip_w1    = (const float*)d_in[11];  // [256,128]
    const float* ip_b1    = (const float*)d_in[12];
    const float* ip_w2    = (const float*)d_in[13];

    float* out = (float*)d_out;
    const int NODE_SZ = BB * NNODE * HID;            // 1048576
    float* raw_pooled = out;
    float* node0 = out + BB * HID;
    float* node1 = node0 + NODE_SZ;
    float* pooled0 = node1 + NODE_SZ;
    float* pooled1 = pooled0 + BB * HID;

    float* x0 = nullptr;
    cudaGetSymbolAddress((void**)&x0, g_x0);

    // input projection
    k_input<<<BB * NNODE * HID / 256, 256>>>(ge, in_w, in_b);

    // raw pooled (on x0)
    run_pool(x0, ip_w1, ip_b1, ip_w2, raw_pooled);

    // layer 0
    k_gemm<<<BB * NNODE / 16, 256>>>(x0, proj_w, attn_src, attn_dst);
    k_agg<<<BB * (NNODE / TI), 256>>>(adj, node0);
    run_pool(node0, pool_w1, pool_b1, pool_w2, pooled0);

    // layer 1
    k_gemm<<<BB * NNODE / 16, 256>>>(node0, proj_w + HID * HID,
                                     attn_src + NH * DD, attn_dst + NH * DD);
    k_agg<<<BB * (NNODE / TI), 256>>>(adj, node1);
    run_pool(node1, pool_w1 + HID * PL, pool_b1 + PL, pool_w2 + PL, pooled1);
}

// round 11
// speedup vs baseline: 1.2271x; 1.1381x over previous
#include <cuda_runtime.h>
#include <math.h>

#define BB   2
#define NNODE 2048
#define HID  256
#define NH   4
#define DD   64
#define PL   128

// ---------------- scratch (device globals; no allocation allowed) ----------------
__device__ float g_x0[BB*NNODE*HID];       // input-proj output (4 MB)
__device__ float g_h[BB*NNODE*HID];        // per-layer projected features (4 MB)
__device__ float4 g_spk[BB*NNODE*NH];      // (src, exp(src), exp(.2src), 0)
__device__ float4 g_dpk[BB*NNODE*NH];      // (dst, exp(dst), exp(.2dst), 0)
__device__ float g_partial[BB*128*HID];    // pool partial weighted sums (unnormalized)
__device__ float g_zpart[BB*128];          // pool partial Z

// ---------------- packed f32x2 helpers (sm_103a) ----------------
__device__ __forceinline__ unsigned long long pack2(float v) {
    unsigned long long r;
    asm("mov.b64 %0, {%1, %1};" : "=l"(r) : "f"(v));
    return r;
}
__device__ __forceinline__ void unpack2(unsigned long long v, float& lo, float& hi) {
    asm("mov.b64 {%0, %1}, %2;" : "=f"(lo), "=f"(hi) : "l"(v));
}
__device__ __forceinline__ unsigned long long fma2(unsigned long long a,
                                                   unsigned long long b,
                                                   unsigned long long c) {
    unsigned long long d;
    asm("fma.rn.f32x2 %0, %1, %2, %3;" : "=l"(d) : "l"(a), "l"(b), "l"(c));
    return d;
}
__device__ __forceinline__ unsigned int smem_u32(const void* p) {
    unsigned int a;
    asm("{ .reg .u64 t; cvta.to.shared.u64 t, %1; cvt.u32.u64 %0, t; }"
        : "=r"(a) : "l"(p));
    return a;
}

// ---------------- input projection: x = relu(ge * w + b) ----------------
__global__ void k_input(const float* __restrict__ ge,
                        const float* __restrict__ w,
                        const float* __restrict__ b) {
    int idx = blockIdx.x * 256 + threadIdx.x;   // over B*N*HID
    int c = idx & (HID - 1);
    float v = fmaf(ge[idx >> 8], w[c], b[c]);
    g_x0[idx] = v > 0.f ? v : 0.f;
}

// ---------------- fused pool: scores -> exp -> weighted partial + Z partial ----
// Block = 16 nodes. s[n] = sum_p tanh(x@w1+b1)_p * w2_p (b2 dropped: shift-inv).
// |s| small => exp without max-subtraction is safe in f32.
// w1 loads batched x4 (independent LDGs) to hide L2 latency.
__global__ void __launch_bounds__(256) k_pool_sb(const float* __restrict__ x,
                                                 const float* __restrict__ w1,
                                                 const float* __restrict__ b1,
                                                 const float* __restrict__ w2) {
    __shared__ float xs[16][HID];      // 16 KB
    __shared__ float red[16][4];
    __shared__ float se[16];
    int b = blockIdx.x >> 7, seg = blockIdx.x & 127;
    int tid = threadIdx.x;
    long n0 = (long)b * NNODE + seg * 16;

    // load 16 rows (1024 float4)
    const float4* s4 = (const float4*)(x + n0 * HID);
    float4* d4 = (float4*)xs;
#pragma unroll
    for (int k = 0; k < 4; k++) d4[tid + k * 256] = s4[tid + k * 256];
    __syncthreads();

    // scores: half = tid>>7 handles rows half*8..+7 with 128 threads (p = tid&127)
    int half = tid >> 7, p = tid & 127;
    float acc[8];
#pragma unroll
    for (int r = 0; r < 8; r++) acc[r] = 0.f;
    for (int c = 0; c < HID; c += 4) {
        float wv0 = w1[(c + 0) * PL + p];
        float wv1 = w1[(c + 1) * PL + p];
        float wv2 = w1[(c + 2) * PL + p];
        float wv3 = w1[(c + 3) * PL + p];
#pragma unroll
        for (int r = 0; r < 8; r++) {
            float4 xv = *(const float4*)&xs[half * 8 + r][c];
            acc[r] = fmaf(xv.x, wv0, acc[r]);
            acc[r] = fmaf(xv.y, wv1, acc[r]);
            acc[r] = fmaf(xv.z, wv2, acc[r]);
            acc[r] = fmaf(xv.w, wv3, acc[r]);
        }
    }
    float bv = b1[p], w2v = w2[p];
    int lane = tid & 31, wp = tid >> 5;    // global warp 0..7; within-half warp = wp&3
#pragma unroll
    for (int r = 0; r < 8; r++) {
        float v = tanhf(acc[r] + bv) * w2v;
#pragma unroll
        for (int off = 16; off; off >>= 1) v += __shfl_down_sync(0xffffffffu, v, off);
        if (lane == 0) red[half * 8 + r][wp & 3] = v;
    }
    __syncthreads();
    if (tid < 16) {
        float s = red[tid][0] + red[tid][1] + red[tid][2] + red[tid][3];
        float e = expf(s);
        se[tid] = e;
        float z = e;
#pragma unroll
        for (int off = 8; off; off >>= 1) z += __shfl_down_sync(0x0000ffffu, z, off, 16);
        if (tid == 0) g_zpart[b * 128 + seg] = z;
    }
    __syncthreads();
    // weighted partial for this segment: acc over 16 rows, column = tid
    float a = 0.f;
#pragma unroll
    for (int r = 0; r < 16; r++) a = fmaf(se[r], xs[r][tid], a);
    g_partial[(b * 128 + seg) * HID + tid] = a;
}

// ---------------- pool finalize: parallel reduce 128 partials + Z, divide ------
__global__ void k_pool_c2(float* __restrict__ outp) {
    __shared__ float chunks[4][64];
    __shared__ float zred[2];
    int b = blockIdx.x >> 2, cg = blockIdx.x & 3;
    int tid = threadIdx.x;
    int c = cg * 64 + (tid & 63), sc = tid >> 6;
    float a = 0.f;
#pragma unroll 8
    for (int k = 0; k < 32; k++)
        a += g_partial[(b * 128 + sc * 32 + k) * HID + c];
    chunks[sc][tid & 63] = a;
    // Z reduce by warp 0
    if (tid < 32) {
        float z = g_zpart[b * 128 + tid] + g_zpart[b * 128 + 32 + tid]
                + g_zpart[b * 128 + 64 + tid] + g_zpart[b * 128 + 96 + tid];
#pragma unroll
        for (int off = 16; off; off >>= 1) z += __shfl_down_sync(0xffffffffu, z, off);
        if (tid == 0) zred[0] = z;
    }
    __syncthreads();
    if (tid < 64) {
        float t = chunks[0][tid] + chunks[1][tid] + chunks[2][tid] + chunks[3][tid];
        outp[b * HID + cg * 64 + tid] = t / zred[0];
    }
}

// ---------------- h = cur @ W, fused src/dst projections + exp tables ----------
// 8 rows/block (grid 512): ~3.5 blocks/SM doubles occupancy vs 16 rows.
// W loads batched x8 (independent LDGs -> MLP 8) to hide L2 latency.
__global__ void __launch_bounds__(256) k_gemm(const float* __restrict__ xin,
                                              const float* __restrict__ W,
                                              const float* __restrict__ asrc,
                                              const float* __restrict__ adst) {
    __shared__ float xs[8][HID];       // 8 KB
    __shared__ float sred[8][8], dred[8][8];
    int row0 = blockIdx.x * 8;
    int tid = threadIdx.x;   // 256 = output column
    const float4* s4 = (const float4*)(xin + row0 * HID);
    float4* d4 = (float4*)xs;
#pragma unroll
    for (int k = 0; k < 2; k++) d4[tid + k * 256] = s4[tid + k * 256];
    __syncthreads();

    float acc[8];
#pragma unroll
    for (int r = 0; r < 8; r++) acc[r] = 0.f;
    for (int c = 0; c < HID; c += 8) {
        float w[8];
#pragma unroll
        for (int u = 0; u < 8; u++) w[u] = W[(c + u) * HID + tid];
#pragma unroll
        for (int r = 0; r < 8; r++) {
            float4 xa = *(const float4*)&xs[r][c];
            float4 xb = *(const float4*)&xs[r][c + 4];
            acc[r] = fmaf(xa.x, w[0], acc[r]);
            acc[r] = fmaf(xa.y, w[1], acc[r]);
            acc[r] = fmaf(xa.z, w[2], acc[r]);
            acc[r] = fmaf(xa.w, w[3], acc[r]);
            acc[r] = fmaf(xb.x, w[4], acc[r]);
            acc[r] = fmaf(xb.y, w[5], acc[r]);
            acc[r] = fmaf(xb.z, w[6], acc[r]);
            acc[r] = fmaf(xb.w, w[7], acc[r]);
        }
    }
#pragma unroll
    for (int r = 0; r < 8; r++) g_h[(row0 + r) * HID + tid] = acc[r];

    // src/dst epilogue: head = col>>6; reduce acc[r]*a over each 64-col head segment
    float as = asrc[tid], ad = adst[tid];
    int lane = tid & 31, wp = tid >> 5;     // warps 2h, 2h+1 cover head h
#pragma unroll
    for (int r = 0; r < 8; r++) {
        float vs = acc[r] * as, vd = acc[r] * ad;
#pragma unroll
        for (int off = 16; off; off >>= 1) {
            vs += __shfl_down_sync(0xffffffffu, vs, off);
            vd += __shfl_down_sync(0xffffffffu, vd, off);
        }
        if (lane == 0) { sred[r][wp] = vs; dred[r][wp] = vd; }
    }
    __syncthreads();
    if (tid < 32) {
        int r = tid & 7, hh = tid >> 3;
        float s = sred[r][2 * hh] + sred[r][2 * hh + 1];
        float d = dred[r][2 * hh] + dred[r][2 * hh + 1];
        int o = (row0 + r) * NH + hh;
        g_spk[o] = make_float4(s, expf(s), expf(0.2f * s), 0.f);
        g_dpk[o] = make_float4(d, expf(d), expf(0.2f * d), 0.f);
    }
}

// ---------------- GAT aggregation + ELU ----------------
// out[b,i,hh*64+d] = elu( (1/Z) * sum_j e_ij * h[j,hh*64+d] )
// e_ij = adj ? (src_i+dst_j>=0 ? exp(src_i)exp(dst_j) : exp(.2src_i)exp(.2dst_j)) : 0
//
// TI=16, TJ=16, DOUBLE-BUFFERED h-tiles via cp.async; wait_group 1 keeps one
// group in flight. Phase-1 dq loads explicitly batched (MLP 4). e-tile
// transposed [h][j][i], slab 272 floats (conflict-free stores, aligned LDS.128).
#define TI 16
#define TJ 16
#define ESLAB 272   // TJ*TI + 16 pad floats per head slab
__global__ void __launch_bounds__(256) k_agg(const int* __restrict__ adj,
                                             float* __restrict__ outn) {
    __shared__ __align__(16) float hs[2][TJ][HID];      // 32 KB (double buffer)
    __shared__ __align__(16) float es2[NH * ESLAB];     // 4.25 KB, [h][j][i]
    __shared__ float zs[TI * NH];                       // 64

    int b  = blockIdx.x >> 7;              // 128 i-tiles per batch
    int i0 = (blockIdx.x & 127) * TI;
    int tid = threadIdx.x;

    if (tid < TI * NH) zs[tid] = 0.f;

    // phase-1 mapping: i_p1 = tid&15, h_p1 = (tid>>4)&3, jg = tid>>6 (0..3)
    int i_p1 = tid & 15;
    int h_p1 = (tid >> 4) & 3;
    int jg   = tid >> 6;                   // j = jg*4 + rep, rep 0..3

    float4 sq = g_spk[(b * NNODE + i0 + i_p1) * NH + h_p1];   // (src, e+, e-)
    const int* __restrict__ arow = adj + b * NNODE * NNODE + (i0 + i_p1) * NNODE + jg * 4;
    const float4* __restrict__ dtab = g_dpk + (b * NNODE) * NH + jg * 4 * NH + h_p1;
    float* __restrict__ eout = es2 + h_p1 * ESLAB + jg * 4 * 16 + i_p1;
    float zloc = 0.f;

    // phase-2 mapping: column = tid, head = tid>>6
    int hh = tid >> 6;
    const float* eslab = es2 + hh * ESLAB;

    // cp.async addressing: each thread fills 4 x 16B per tile buffer
    unsigned int hs0 = smem_u32(hs) + (unsigned int)tid * 16u;
    const float4* hsrc_base = (const float4*)(g_h + b * NNODE * HID) + tid;

    unsigned long long acc2[8];            // row-pairs (0,1)...(14,15)
#pragma unroll
    for (int r = 0; r < 8; r++) acc2[r] = 0ull;

    // prologue: issue tile 0 into buffer 0
    {
        const float4* src = hsrc_base;
#pragma unroll
        for (int k = 0; k < 4; k++)
            asm volatile("cp.async.cg.shared.global [%0], [%1], 16;"
                         :: "r"(hs0 + k * 4096u), "l"(src + k * 256) : "memory");
        asm volatile("cp.async.commit_group;" ::: "memory");
    }

    const int NT = NNODE / TJ;   // 128 tiles
    for (int jt = 0; jt < NT; jt++) {
        int j0 = jt * TJ;
        int cur = jt & 1;
        __syncthreads();   // phase2(jt-1) done: es2 free, buf cur^1 free
        // issue next tile into the other buffer
        if (jt + 1 < NT) {
            const float4* src = hsrc_base + (j0 + TJ) * (HID / 4);
            unsigned int dst = hs0 + (unsigned int)(cur ^ 1) * 16384u;
#pragma unroll
            for (int k = 0; k < 4; k++)
                asm volatile("cp.async.cg.shared.global [%0], [%1], 16;"
                             :: "r"(dst + k * 4096u), "l"(src + k * 256) : "memory");
            asm volatile("cp.async.commit_group;" ::: "memory");
        }
        // phase 1: e for (i_p1, j = jg*4+rep, h_p1); adj + all dq batched first
        {
            int4 aa = *(const int4*)(arow + j0);
            const float4* dq4 = dtab + j0 * NH;
            float4 dq0 = dq4[0 * NH];
            float4 dq1 = dq4[1 * NH];
            float4 dq2 = dq4[2 * NH];
            float4 dq3 = dq4[3 * NH];
            int av[4] = {aa.x, aa.y, aa.z, aa.w};
            float4 dqv[4] = {dq0, dq1, dq2, dq3};
#pragma unroll
            for (int rep = 0; rep < 4; rep++) {
                float4 dq = dqv[rep];
                float sv = sq.x + dq.x;
                float e = 0.f;
                if (av[rep] > 0) e = (sv >= 0.f) ? sq.y * dq.y : sq.z * dq.z;
                eout[rep * 16] = e;
                zloc += e;
            }
        }
        // wait for THIS tile's data (1 newer group may stay in flight)
        if (jt + 1 < NT) asm volatile("cp.async.wait_group 1;" ::: "memory");
        else             asm volatile("cp.async.wait_group 0;" ::: "memory");
        __syncthreads();   // hs[cur] filled + es2 visible
        // phase 2: acc[row-pair] += e2 * {hv,hv}
#pragma unroll 8
        for (int j = 0; j < TJ; j++) {
            unsigned long long hv2 = pack2(hs[cur][j][tid]);
            const ulonglong2* ep = (const ulonglong2*)(eslab + j * 16);
            ulonglong2 e0 = ep[0];   // rows (0,1),(2,3)
            ulonglong2 e1 = ep[1];   // rows (4,5),(6,7)
            ulonglong2 e2 = ep[2];   // rows (8,9),(10,11)
            ulonglong2 e3 = ep[3];   // rows (12,13),(14,15)
            acc2[0] = fma2(e0.x, hv2, acc2[0]);
            acc2[1] = fma2(e0.y, hv2, acc2[1]);
            acc2[2] = fma2(e1.x, hv2, acc2[2]);
            acc2[3] = fma2(e1.y, hv2, acc2[3]);
            acc2[4] = fma2(e2.x, hv2, acc2[4]);
            acc2[5] = fma2(e2.y, hv2, acc2[5]);
            acc2[6] = fma2(e3.x, hv2, acc2[6]);
            acc2[7] = fma2(e3.y, hv2, acc2[7]);
        }
    }
    // reduce Z: one atomic per thread (4 jg threads per (i,h) slot)
    atomicAdd(&zs[i_p1 * NH + h_p1], zloc);
    __syncthreads();
    // epilogue: normalize + ELU, write node output
#pragma unroll
    for (int r = 0; r < 8; r++) {
        float v0, v1;
        unpack2(acc2[r], v0, v1);
        int ia = 2 * r, ib = 2 * r + 1;
        float r0 = v0 / zs[ia * NH + hh];
        float r1 = v1 / zs[ib * NH + hh];
        outn[(b * NNODE + i0 + ia) * HID + tid] = (r0 > 0.f) ? r0 : expm1f(r0);
        outn[(b * NNODE + i0 + ib) * HID + tid] = (r1 > 0.f) ? r1 : expm1f(r1);
    }
}

// ---------------- host orchestration ----------------
static void run_pool(const float* x, const float* w1, const float* b1,
                     const float* w2, float* outp) {
    k_pool_sb<<<BB * 128, 256>>>(x, w1, b1, w2);
    k_pool_c2<<<BB * 4, 256>>>(outp);
}

extern "C" void kernel_launch(void* const* d_in, const int* in_sizes, int n_in,
                              void* d_out, int out_size) {
    const float* ge       = (const float*)d_in[0];
    const int*   adj      = (const int*)  d_in[1];
    const float* in_w     = (const float*)d_in[2];
    const float* in_b     = (const float*)d_in[3];
    const float* proj_w   = (const float*)d_in[4];   // [2,256,256]
    const float* attn_src = (const float*)d_in[5];   // [2,4,64]
    const float* attn_dst = (const float*)d_in[6];
    const float* pool_w1  = (const float*)d_in[7];   // [2,256,128]
    const float* pool_b1  = (const float*)d_in[8];   // [2,128]
    const float* pool_w2  = (const float*)d_in[9];   // [2,128]
    const float* ip_w1    = (const float*)d_in[11];  // [256,128]
    const float* ip_b1    = (const float*)d_in[12];
    const float* ip_w2    = (const float*)d_in[13];

    float* out = (float*)d_out;
    const int NODE_SZ = BB * NNODE * HID;            // 1048576
    float* raw_pooled = out;
    float* node0 = out + BB * HID;
    float* node1 = node0 + NODE_SZ;
    float* pooled0 = node1 + NODE_SZ;
    float* pooled1 = pooled0 + BB * HID;

    float* x0 = nullptr;
    cudaGetSymbolAddress((void**)&x0, g_x0);

    // input projection
    k_input<<<BB * NNODE * HID / 256, 256>>>(ge, in_w, in_b);

    // raw pooled (on x0)
    run_pool(x0, ip_w1, ip_b1, ip_w2, raw_pooled);

    // layer 0
    k_gemm<<<BB * NNODE / 8, 256>>>(x0, proj_w, attn_src, attn_dst);
    k_agg<<<BB * (NNODE / TI), 256>>>(adj, node0);
    run_pool(node0, pool_w1, pool_b1, pool_w2, pooled0);

    // layer 1
    k_gemm<<<BB * NNODE / 8, 256>>>(node0, proj_w + HID * HID,
                                    attn_src + NH * DD, attn_dst + NH * DD);
    k_agg<<<BB * (NNODE / TI), 256>>>(adj, node1);
    run_pool(node1, pool_w1 + HID * PL, pool_b1 + PL, pool_w2 + PL, pooled1);
}

// round 13
// speedup vs baseline: 1.4849x; 1.2101x over previous
#include <cuda_runtime.h>
#include <math.h>

#define BB   2
#define NNODE 2048
#define HID  256
#define NH   4
#define DD   64
#define PL   128

// ---------------- scratch (device globals; no allocation allowed) ----------------
__device__ float g_x0[BB*NNODE*HID];       // input-proj output (4 MB)
__device__ float g_h[BB*NNODE*HID];        // per-layer projected features (4 MB)
__device__ float4 g_spk[BB*NNODE*NH];      // (src, exp(src), exp(.2src), 0)
__device__ float4 g_dpk[BB*NNODE*NH];      // (dst, exp(dst), exp(.2dst), 0)
__device__ float g_partial[BB*128*HID];    // pool partial weighted sums (unnormalized)
__device__ float g_zpart[BB*128];          // pool partial Z

// ---------------- packed f32x2 helpers (sm_103a) ----------------
__device__ __forceinline__ unsigned long long pack2(float v) {
    unsigned long long r;
    asm("mov.b64 %0, {%1, %1};" : "=l"(r) : "f"(v));
    return r;
}
__device__ __forceinline__ void unpack2(unsigned long long v, float& lo, float& hi) {
    asm("mov.b64 {%0, %1}, %2;" : "=f"(lo), "=f"(hi) : "l"(v));
}
__device__ __forceinline__ unsigned long long fma2(unsigned long long a,
                                                   unsigned long long b,
                                                   unsigned long long c) {
    unsigned long long d;
    asm("fma.rn.f32x2 %0, %1, %2, %3;" : "=l"(d) : "l"(a), "l"(b), "l"(c));
    return d;
}
__device__ __forceinline__ unsigned long long add2(unsigned long long a,
                                                   unsigned long long b) {
    unsigned long long d;
    asm("add.rn.f32x2 %0, %1, %2;" : "=l"(d) : "l"(a), "l"(b));
    return d;
}
__device__ __forceinline__ unsigned int smem_u32(const void* p) {
    unsigned int a;
    asm("{ .reg .u64 t; cvta.to.shared.u64 t, %1; cvt.u32.u64 %0, t; }"
        : "=r"(a) : "l"(p));
    return a;
}

// ---------------- input projection: x = relu(ge * w + b) ----------------
__global__ void k_input(const float* __restrict__ ge,
                        const float* __restrict__ w,
                        const float* __restrict__ b) {
    int idx = blockIdx.x * 256 + threadIdx.x;   // over B*N*HID
    int c = idx & (HID - 1);
    float v = fmaf(ge[idx >> 8], w[c], b[c]);
    g_x0[idx] = v > 0.f ? v : 0.f;
}

// ---------------- fused pool: scores -> exp -> weighted partial + Z partial ----
__global__ void __launch_bounds__(256) k_pool_sb(const float* __restrict__ x,
                                                 const float* __restrict__ w1,
                                                 const float* __restrict__ b1,
                                                 const float* __restrict__ w2) {
    __shared__ float xs[16][HID];      // 16 KB
    __shared__ float red[16][4];
    __shared__ float se[16];
    int b = blockIdx.x >> 7, seg = blockIdx.x & 127;
    int tid = threadIdx.x;
    long n0 = (long)b * NNODE + seg * 16;

    const float4* s4 = (const float4*)(x + n0 * HID);
    float4* d4 = (float4*)xs;
#pragma unroll
    for (int k = 0; k < 4; k++) d4[tid + k * 256] = s4[tid + k * 256];
    __syncthreads();

    int half = tid >> 7, p = tid & 127;
    float acc[8];
#pragma unroll
    for (int r = 0; r < 8; r++) acc[r] = 0.f;
    for (int c = 0; c < HID; c += 4) {
        float wv0 = w1[(c + 0) * PL + p];
        float wv1 = w1[(c + 1) * PL + p];
        float wv2 = w1[(c + 2) * PL + p];
        float wv3 = w1[(c + 3) * PL + p];
#pragma unroll
        for (int r = 0; r < 8; r++) {
            float4 xv = *(const float4*)&xs[half * 8 + r][c];
            acc[r] = fmaf(xv.x, wv0, acc[r]);
            acc[r] = fmaf(xv.y, wv1, acc[r]);
            acc[r] = fmaf(xv.z, wv2, acc[r]);
            acc[r] = fmaf(xv.w, wv3, acc[r]);
        }
    }
    float bv = b1[p], w2v = w2[p];
    int lane = tid & 31, wp = tid >> 5;
#pragma unroll
    for (int r = 0; r < 8; r++) {
        float v = tanhf(acc[r] + bv) * w2v;
#pragma unroll
        for (int off = 16; off; off >>= 1) v += __shfl_down_sync(0xffffffffu, v, off);
        if (lane == 0) red[half * 8 + r][wp & 3] = v;
    }
    __syncthreads();
    if (tid < 16) {
        float s = red[tid][0] + red[tid][1] + red[tid][2] + red[tid][3];
        float e = expf(s);
        se[tid] = e;
        float z = e;
#pragma unroll
        for (int off = 8; off; off >>= 1) z += __shfl_down_sync(0x0000ffffu, z, off, 16);
        if (tid == 0) g_zpart[b * 128 + seg] = z;
    }
    __syncthreads();
    float a = 0.f;
#pragma unroll
    for (int r = 0; r < 16; r++) a = fmaf(se[r], xs[r][tid], a);
    g_partial[(b * 128 + seg) * HID + tid] = a;
}

// ---------------- pool finalize: parallel reduce 128 partials + Z, divide ------
__global__ void k_pool_c2(float* __restrict__ outp) {
    __shared__ float chunks[4][64];
    __shared__ float zred[2];
    int b = blockIdx.x >> 2, cg = blockIdx.x & 3;
    int tid = threadIdx.x;
    int c = cg * 64 + (tid & 63), sc = tid >> 6;
    float a = 0.f;
#pragma unroll 8
    for (int k = 0; k < 32; k++)
        a += g_partial[(b * 128 + sc * 32 + k) * HID + c];
    chunks[sc][tid & 63] = a;
    if (tid < 32) {
        float z = g_zpart[b * 128 + tid] + g_zpart[b * 128 + 32 + tid]
                + g_zpart[b * 128 + 64 + tid] + g_zpart[b * 128 + 96 + tid];
#pragma unroll
        for (int off = 16; off; off >>= 1) z += __shfl_down_sync(0xffffffffu, z, off);
        if (tid == 0) zred[0] = z;
    }
    __syncthreads();
    if (tid < 64) {
        float t = chunks[0][tid] + chunks[1][tid] + chunks[2][tid] + chunks[3][tid];
        outp[b * HID + cg * 64 + tid] = t / zred[0];
    }
}

// ---------------- h = cur @ W, fused src/dst projections + exp tables ----------
__global__ void __launch_bounds__(256) k_gemm(const float* __restrict__ xin,
                                              const float* __restrict__ W,
                                              const float* __restrict__ asrc,
                                              const float* __restrict__ adst) {
    __shared__ float xs[8][HID];       // 8 KB
    __shared__ float sred[8][8], dred[8][8];
    int row0 = blockIdx.x * 8;
    int tid = threadIdx.x;
    const float4* s4 = (const float4*)(xin + row0 * HID);
    float4* d4 = (float4*)xs;
#pragma unroll
    for (int k = 0; k < 2; k++) d4[tid + k * 256] = s4[tid + k * 256];
    __syncthreads();

    float acc[8];
#pragma unroll
    for (int r = 0; r < 8; r++) acc[r] = 0.f;
    for (int c = 0; c < HID; c += 8) {
        float w[8];
#pragma unroll
        for (int u = 0; u < 8; u++) w[u] = W[(c + u) * HID + tid];
#pragma unroll
        for (int r = 0; r < 8; r++) {
            float4 xa = *(const float4*)&xs[r][c];
            float4 xb = *(const float4*)&xs[r][c + 4];
            acc[r] = fmaf(xa.x, w[0], acc[r]);
            acc[r] = fmaf(xa.y, w[1], acc[r]);
            acc[r] = fmaf(xa.z, w[2], acc[r]);
            acc[r] = fmaf(xa.w, w[3], acc[r]);
            acc[r] = fmaf(xb.x, w[4], acc[r]);
            acc[r] = fmaf(xb.y, w[5], acc[r]);
            acc[r] = fmaf(xb.z, w[6], acc[r]);
            acc[r] = fmaf(xb.w, w[7], acc[r]);
        }
    }
#pragma unroll
    for (int r = 0; r < 8; r++) g_h[(row0 + r) * HID + tid] = acc[r];

    float as = asrc[tid], ad = adst[tid];
    int lane = tid & 31, wp = tid >> 5;
#pragma unroll
    for (int r = 0; r < 8; r++) {
        float vs = acc[r] * as, vd = acc[r] * ad;
#pragma unroll
        for (int off = 16; off; off >>= 1) {
            vs += __shfl_down_sync(0xffffffffu, vs, off);
            vd += __shfl_down_sync(0xffffffffu, vd, off);
        }
        if (lane == 0) { sred[r][wp] = vs; dred[r][wp] = vd; }
    }
    __syncthreads();
    if (tid < 32) {
        int r = tid & 7, hh = tid >> 3;
        float s = sred[r][2 * hh] + sred[r][2 * hh + 1];
        float d = dred[r][2 * hh] + dred[r][2 * hh + 1];
        int o = (row0 + r) * NH + hh;
        g_spk[o] = make_float4(s, expf(s), expf(0.2f * s), 0.f);
        g_dpk[o] = make_float4(d, expf(d), expf(0.2f * d), 0.f);
    }
}

// ---------------- GAT aggregation + ELU ----------------
// Phase-2 j-pair half-warp scheme: lanes 0-15 process even j, lanes 16-31 odd j;
// each lane covers 2 columns (cross-assigned so every LDS has two bank-disjoint
// half-warp address groups -> 1 crossbar phase each, no broadcast waste).
// Per warp per j-pair: 4 e-LDS.128 + 2 h-LDS + 2 pack + 16 fma2 = 24 issues,
// 6 phases (vs 28 issues / 10 phases before). Cross-half combine via shfl+add2.
#define TI 16
#define TJ 16
#define ESLAB 272   // TJ*TI + 16 pad floats per head slab
__global__ void __launch_bounds__(256) k_agg(const int* __restrict__ adj,
                                             float* __restrict__ outn) {
    __shared__ __align__(16) float hs[2][TJ][HID];      // 32 KB (double buffer)
    __shared__ __align__(16) float es2[NH * ESLAB];     // 4.25 KB, [h][j][i]
    __shared__ float zs[TI * NH];                       // 64

    int b  = blockIdx.x >> 7;              // 128 i-tiles per batch
    int i0 = (blockIdx.x & 127) * TI;
    int tid = threadIdx.x;

    if (tid < TI * NH) zs[tid] = 0.f;

    // phase-1 mapping (unchanged): i_p1 = tid&15, h_p1 = (tid>>4)&3, jg = tid>>6
    int i_p1 = tid & 15;
    int h_p1 = (tid >> 4) & 3;
    int jg   = tid >> 6;                   // j = jg*4 + rep, rep 0..3

    float4 sq = g_spk[(b * NNODE + i0 + i_p1) * NH + h_p1];
    const int* __restrict__ arow = adj + b * NNODE * NNODE + (i0 + i_p1) * NNODE + jg * 4;
    const float4* __restrict__ dtab = g_dpk + (b * NNODE) * NH + jg * 4 * NH + h_p1;
    float* __restrict__ eout = es2 + h_p1 * ESLAB + jg * 4 * 16 + i_p1;
    float zloc = 0.f;

    // phase-2 mapping: warp w covers cols [32w,32w+32); hh = w>>1 (uniform/warp)
    int w    = tid >> 5;
    int lane = tid & 31;
    int cl   = lane & 15;
    int jpar = lane >> 4;                  // 0: even j, 1: odd j
    int hh   = tid >> 6;
    const float* eslab = es2 + hh * ESLAB;
    int c1 = 32 * w + cl + 16 * jpar;      // this lane's primary column
    int c2 = 32 * w + cl + 16 * (1 - jpar);

    // cp.async addressing: each thread fills 4 x 16B per tile buffer
    unsigned int hs0 = smem_u32(hs) + (unsigned int)tid * 16u;
    const float4* hsrc_base = (const float4*)(g_h + b * NNODE * HID) + tid;

    unsigned long long accP[8], accQ[8];   // row-pairs for cols c1 / c2 (this lane's j-parity)
#pragma unroll
    for (int r = 0; r < 8; r++) { accP[r] = 0ull; accQ[r] = 0ull; }

    // prologue: issue tile 0 into buffer 0
    {
        const float4* src = hsrc_base;
#pragma unroll
        for (int k = 0; k < 4; k++)
            asm volatile("cp.async.cg.shared.global [%0], [%1], 16;"
                         :: "r"(hs0 + k * 4096u), "l"(src + k * 256) : "memory");
        asm volatile("cp.async.commit_group;" ::: "memory");
    }

    const int NT = NNODE / TJ;   // 128 tiles
    for (int jt = 0; jt < NT; jt++) {
        int j0 = jt * TJ;
        int cur = jt & 1;
        __syncthreads();   // phase2(jt-1) done: es2 free, buf cur^1 free
        if (jt + 1 < NT) {
            const float4* src = hsrc_base + (j0 + TJ) * (HID / 4);
            unsigned int dst = hs0 + (unsigned int)(cur ^ 1) * 16384u;
#pragma unroll
            for (int k = 0; k < 4; k++)
                asm volatile("cp.async.cg.shared.global [%0], [%1], 16;"
                             :: "r"(dst + k * 4096u), "l"(src + k * 256) : "memory");
            asm volatile("cp.async.commit_group;" ::: "memory");
        }
        // phase 1: e for (i_p1, j = jg*4+rep, h_p1); adj + dq batched
        {
            int4 aa = *(const int4*)(arow + j0);
            const float4* dq4 = dtab + j0 * NH;
            float4 dq0 = dq4[0 * NH];
            float4 dq1 = dq4[1 * NH];
            float4 dq2 = dq4[2 * NH];
            float4 dq3 = dq4[3 * NH];
            int av[4] = {aa.x, aa.y, aa.z, aa.w};
            float4 dqv[4] = {dq0, dq1, dq2, dq3};
#pragma unroll
            for (int rep = 0; rep < 4; rep++) {
                float4 dq = dqv[rep];
                float sv = sq.x + dq.x;
                float e = 0.f;
                if (av[rep] > 0) e = (sv >= 0.f) ? sq.y * dq.y : sq.z * dq.z;
                eout[rep * 16] = e;
                zloc += e;
            }
        }
        if (jt + 1 < NT) asm volatile("cp.async.wait_group 1;" ::: "memory");
        else             asm volatile("cp.async.wait_group 0;" ::: "memory");
        __syncthreads();   // hs[cur] filled + es2 visible
        // phase 2: j-pairs; this lane handles j = 2t + jpar for cols c1, c2
#pragma unroll 4
        for (int t = 0; t < TJ / 2; t++) {
            int jj = 2 * t + jpar;
            const ulonglong2* ep = (const ulonglong2*)(eslab + jj * 16);
            ulonglong2 e0 = ep[0];   // rows (0,1),(2,3)
            ulonglong2 e1 = ep[1];   // rows (4,5),(6,7)
            const float* hrow = hs[cur][jj];
            unsigned long long hv1 = pack2(hrow[c1]);
            unsigned long long hv2 = pack2(hrow[c2]);
            ulonglong2 e2 = ep[2];   // rows (8,9),(10,11)
            ulonglong2 e3 = ep[3];   // rows (12,13),(14,15)
            accP[0] = fma2(e0.x, hv1, accP[0]);  accQ[0] = fma2(e0.x, hv2, accQ[0]);
            accP[1] = fma2(e0.y, hv1, accP[1]);  accQ[1] = fma2(e0.y, hv2, accQ[1]);
            accP[2] = fma2(e1.x, hv1, accP[2]);  accQ[2] = fma2(e1.x, hv2, accQ[2]);
            accP[3] = fma2(e1.y, hv1, accP[3]);  accQ[3] = fma2(e1.y, hv2, accQ[3]);
            accP[4] = fma2(e2.x, hv1, accP[4]);  accQ[4] = fma2(e2.x, hv2, accQ[4]);
            accP[5] = fma2(e2.y, hv1, accP[5]);  accQ[5] = fma2(e2.y, hv2, accQ[5]);
            accP[6] = fma2(e3.x, hv1, accP[6]);  accQ[6] = fma2(e3.x, hv2, accQ[6]);
            accP[7] = fma2(e3.y, hv1, accP[7]);  accQ[7] = fma2(e3.y, hv2, accQ[7]);
        }
    }
    // reduce Z: one atomic per thread (4 jg threads per (i,h) slot)
    atomicAdd(&zs[i_p1 * NH + h_p1], zloc);

    // cross-half combine: lane l (<16) gets the odd-j partials from lane l+16.
    // For lane l: accP=colA(even j), accQ=colB(even j); from l+16: accP=colB(odd),
    // accQ=colA(odd). So fA = accP + shfl(accQ), fB = accQ + shfl(accP).
    unsigned long long fA[8], fB[8];
#pragma unroll
    for (int r = 0; r < 8; r++) {
        unsigned long long oq = __shfl_down_sync(0xffffffffu, accQ[r], 16);
        unsigned long long op = __shfl_down_sync(0xffffffffu, accP[r], 16);
        fA[r] = add2(accP[r], oq);
        fB[r] = add2(accQ[r], op);
    }
    __syncthreads();   // zs complete
    // epilogue: lanes 0-15 of each warp write cols colA=32w+cl, colB=colA+16
    if (lane < 16) {
        int colA = 32 * w + cl, colB = colA + 16;
#pragma unroll
        for (int r = 0; r < 8; r++) {
            int ia = 2 * r, ib = 2 * r + 1;
            float zA = zs[ia * NH + hh], zB = zs[ib * NH + hh];
            float a0, a1, b0, b1;
            unpack2(fA[r], a0, a1);
            unpack2(fB[r], b0, b1);
            float ra0 = a0 / zA, ra1 = a1 / zB;
            float rb0 = b0 / zA, rb1 = b1 / zB;
            long base = (long)(b * NNODE + i0) * HID;
            outn[base + (long)ia * HID + colA] = (ra0 > 0.f) ? ra0 : expm1f(ra0);
            outn[base + (long)ib * HID + colA] = (ra1 > 0.f) ? ra1 : expm1f(ra1);
            outn[base + (long)ia * HID + colB] = (rb0 > 0.f) ? rb0 : expm1f(rb0);
            outn[base + (long)ib * HID + colB] = (rb1 > 0.f) ? rb1 : expm1f(rb1);
        }
    }
}

// ---------------- host orchestration ----------------
static void run_pool(const float* x, const float* w1, const float* b1,
                     const float* w2, float* outp) {
    k_pool_sb<<<BB * 128, 256>>>(x, w1, b1, w2);
    k_pool_c2<<<BB * 4, 256>>>(outp);
}

extern "C" void kernel_launch(void* const* d_in, const int* in_sizes, int n_in,
                              void* d_out, int out_size) {
    const float* ge       = (const float*)d_in[0];
    const int*   adj      = (const int*)  d_in[1];
    const float* in_w     = (const float*)d_in[2];
    const float* in_b     = (const float*)d_in[3];
    const float* proj_w   = (const float*)d_in[4];   // [2,256,256]
    const float* attn_src = (const float*)d_in[5];   // [2,4,64]
    const float* attn_dst = (const float*)d_in[6];
    const float* pool_w1  = (const float*)d_in[7];   // [2,256,128]
    const float* pool_b1  = (const float*)d_in[8];   // [2,128]
    const float* pool_w2  = (const float*)d_in[9];   // [2,128]
    const float* ip_w1    = (const float*)d_in[11];  // [256,128]
    const float* ip_b1    = (const float*)d_in[12];
    const float* ip_w2    = (const float*)d_in[13];

    float* out = (float*)d_out;
    const int NODE_SZ = BB * NNODE * HID;            // 1048576
    float* raw_pooled = out;
    float* node0 = out + BB * HID;
    float* node1 = node0 + NODE_SZ;
    float* pooled0 = node1 + NODE_SZ;
    float* pooled1 = pooled0 + BB * HID;

    float* x0 = nullptr;
    cudaGetSymbolAddress((void**)&x0, g_x0);

    // input projection
    k_input<<<BB * NNODE * HID / 256, 256>>>(ge, in_w, in_b);

    // raw pooled (on x0)
    run_pool(x0, ip_w1, ip_b1, ip_w2, raw_pooled);

    // layer 0
    k_gemm<<<BB * NNODE / 8, 256>>>(x0, proj_w, attn_src, attn_dst);
    k_agg<<<BB * (NNODE / TI), 256>>>(adj, node0);
    run_pool(node0, pool_w1, pool_b1, pool_w2, pooled0);

    // layer 1
    k_gemm<<<BB * NNODE / 8, 256>>>(node0, proj_w + HID * HID,
                                    attn_src + NH * DD, attn_dst + NH * DD);
    k_agg<<<BB * (NNODE / TI), 256>>>(adj, node1);
    run_pool(node1, pool_w1 + HID * PL, pool_b1 + PL, pool_w2 + PL, pooled1);
}